// round 4
// baseline (speedup 1.0000x reference)
#include <cuda_runtime.h>
#include <math.h>

// Problem constants
#define BB 32
#define LL 2880
#define CC 862
#define PREDP 720
#define SEGS 48
#define NMM 4
#define KK 16
#define STRIDEV 8
#define NINV 60
#define NOUTV 15
#define CDIMV 359

#define CPB 8              // channels per block
#define XROW 2884          // padded smem row length (floats)
#define NTHR 512
#define CBLKS ((CC + CPB - 1) / CPB)   // 108

// dynamic smem layout (floats):
//   xs   : CPB*XROW = 23072   raw x  -> (reused) staged outputs
//   wbuf : 3840
//       phase1: [0..2047]  stats partials, [2048..3483] staged gate_w
//       phase3: [0..2047]  gate partials,  [2048..3483] gate_w
//       phase4: [0..3839]  W_eff^T  4ch x [60 i][16 o-padded]
//   cw 128, gts 32, meanv 8, stdv 8, istdv 8, bfin 60, cbs 8
#define SMEM_FLOATS (CPB*XROW + 3840 + 128 + 32 + 8 + 8 + 8 + 60 + 8)

__global__ __launch_bounds__(NTHR, 2)
void fused_model_kernel(const float* __restrict__ x,
                        const float* __restrict__ conv_w,
                        const float* __restrict__ conv_b,
                        const float* __restrict__ gate_w,
                        const float* __restrict__ gate_b,
                        const float* __restrict__ map_w,
                        const float* __restrict__ map_b,
                        float* __restrict__ out)
{
    extern __shared__ float sm[];
    float* xs    = sm;                    // 23072
    float* wbuf  = xs + CPB * XROW;       // 3840
    float* cw    = wbuf + 3840;           // 128
    float* gts   = cw + 128;              // 32
    float* meanv = gts + 32;              // 8
    float* stdv  = meanv + 8;             // 8
    float* istdv = stdv + 8;              // 8
    float* bfin  = istdv + 8;             // 60
    float* cbs   = bfin + 60;             // 8

    const int t  = threadIdx.x;
    const int b  = blockIdx.x / CBLKS;
    const int c0 = (blockIdx.x % CBLKS) * CPB;

    // ---- phase 0: per-channel conv weights/bias ----
    if (t < CPB * KK) {
        int ch = t >> 4, k = t & 15;
        int c = c0 + ch;
        cw[t] = (c < CC) ? conv_w[c * KK + k] : 0.f;
    }
    if (t >= 128 && t < 128 + CPB) {
        int c = c0 + (t - 128);
        cbs[t - 128] = (c < CC) ? conv_b[c] : 0.f;
    }

    // ---- phase 1: load raw x slice (float2, channel pairs) + stats partials ----
    {
        const int pr   = t & 3;           // channel pair 0..3
        const int lane = t >> 2;          // 0..127
        const int c    = c0 + pr * 2;
        const bool v0 = (c < CC), v1 = (c + 1 < CC);
        const float* xb = x + (size_t)b * LL * CC + c;
        float* r0 = xs + (pr * 2) * XROW;
        float* r1 = r0 + XROW;
        float s0 = 0.f, q0 = 0.f, s1 = 0.f, q1 = 0.f;
        if (v1) {
            #pragma unroll 4
            for (int l = lane; l < LL; l += 128) {
                float2 vv = *(const float2*)(xb + (size_t)l * CC);
                r0[l] = vv.x; r1[l] = vv.y;
                s0 += vv.x; q0 = fmaf(vv.x, vv.x, q0);
                s1 += vv.y; q1 = fmaf(vv.y, vv.y, q1);
            }
        } else {
            for (int l = lane; l < LL; l += 128) {
                float a = v0 ? __ldg(xb + (size_t)l * CC) : 0.f;
                r0[l] = a; r1[l] = 0.f;
                s0 += a; q0 = fmaf(a, a, q0);
            }
        }
        int ch = pr * 2;
        wbuf[ch * 128 + lane]              = s0;
        wbuf[1024 + ch * 128 + lane]       = q0;
        wbuf[(ch + 1) * 128 + lane]        = s1;
        wbuf[1024 + (ch + 1) * 128 + lane] = q1;
    }
    // stage gate_w into wbuf[2048..3483] (disjoint from stats partials)
    for (int i = t; i < NMM * CDIMV; i += NTHR)
        wbuf[2048 + i] = __ldg(gate_w + i);
    __syncthreads();

    // ---- stats reduction: one warp per channel ----
    if (t < 256) {
        int ch = t >> 5, j = t & 31;
        float s  = wbuf[ch * 128 + j] + wbuf[ch * 128 + j + 32]
                 + wbuf[ch * 128 + j + 64] + wbuf[ch * 128 + j + 96];
        float s2 = wbuf[1024 + ch * 128 + j] + wbuf[1024 + ch * 128 + j + 32]
                 + wbuf[1024 + ch * 128 + j + 64] + wbuf[1024 + ch * 128 + j + 96];
        #pragma unroll
        for (int off = 16; off; off >>= 1) {
            s  += __shfl_down_sync(0xffffffff, s,  off);
            s2 += __shfl_down_sync(0xffffffff, s2, off);
        }
        if (j == 0) {
            float mean = s * (1.f / LL);
            float var  = fmaxf(s2 * (1.f / LL) - mean * mean, 0.f);
            float sd   = sqrtf(var + 1e-10f);
            meanv[ch] = mean;
            stdv[ch]  = sd;
            istdv[ch] = 1.f / sd;
        }
    }
    __syncthreads();

    // ---- phase 3: depthwise conv on RAW x + gate logit partials ----
    {
        const int ch = t >> 6, dl = t & 63;   // 64 d-lanes per channel
        const float4* kwp = (const float4*)(cw + ch * 16);
        const float4 kA = kwp[0], kB = kwp[1], kC = kwp[2], kD = kwp[3];
        const float ksum = kA.x + kA.y + kA.z + kA.w + kB.x + kB.y + kB.z + kB.w
                         + kC.x + kC.y + kC.z + kC.w + kD.x + kD.y + kD.z + kD.w;
        const float scale  = istdv[ch];
        const float offset = cbs[ch] - meanv[ch] * ksum * scale;
        const float* row = xs + ch * XROW;
        const float* gws = wbuf + 2048;
        float a0 = 0.f, a1 = 0.f, a2 = 0.f, a3 = 0.f;
        #pragma unroll
        for (int j = 0; j < 6; j++) {
            int d = dl + 64 * j;
            if (d < CDIMV) {
                const float4* base = (const float4*)(row + 8 * d);
                float4 w0 = base[0], w1 = base[1], w2 = base[2], w3 = base[3];
                float dot = 0.f;
                dot = fmaf(w0.x, kA.x, dot); dot = fmaf(w0.y, kA.y, dot);
                dot = fmaf(w0.z, kA.z, dot); dot = fmaf(w0.w, kA.w, dot);
                dot = fmaf(w1.x, kB.x, dot); dot = fmaf(w1.y, kB.y, dot);
                dot = fmaf(w1.z, kB.z, dot); dot = fmaf(w1.w, kB.w, dot);
                dot = fmaf(w2.x, kC.x, dot); dot = fmaf(w2.y, kC.y, dot);
                dot = fmaf(w2.z, kC.z, dot); dot = fmaf(w2.w, kC.w, dot);
                dot = fmaf(w3.x, kD.x, dot); dot = fmaf(w3.y, kD.y, dot);
                dot = fmaf(w3.z, kD.z, dot); dot = fmaf(w3.w, kD.w, dot);
                float cv = fmaf(dot, scale, offset);
                a0 = fmaf(cv, gws[d],             a0);
                a1 = fmaf(cv, gws[CDIMV + d],     a1);
                a2 = fmaf(cv, gws[2 * CDIMV + d], a2);
                a3 = fmaf(cv, gws[3 * CDIMV + d], a3);
            }
        }
        float* rp = wbuf + ch * 256 + dl * 4;
        rp[0] = a0; rp[1] = a1; rp[2] = a2; rp[3] = a3;
    }
    __syncthreads();
    if (t < 32) {
        int ch = t >> 2, m = t & 3;
        float s = 0.f;
        #pragma unroll
        for (int dl = 0; dl < 64; dl++) s += wbuf[ch * 256 + dl * 4 + m];
        gts[ch * 4 + m] = s + __ldg(gate_b + m);
    }
    __syncthreads();
    if (t < CPB) {
        float g0 = gts[t * 4], g1 = gts[t * 4 + 1], g2 = gts[t * 4 + 2], g3 = gts[t * 4 + 3];
        float mx = fmaxf(fmaxf(g0, g1), fmaxf(g2, g3));
        g0 = expf(g0 - mx); g1 = expf(g1 - mx); g2 = expf(g2 - mx); g3 = expf(g3 - mx);
        float inv = 1.f / (g0 + g1 + g2 + g3);
        gts[t * 4]     = g0 * inv;
        gts[t * 4 + 1] = g1 * inv;
        gts[t * 4 + 2] = g2 * inv;
        gts[t * 4 + 3] = g3 * inv;
    }
    __syncthreads();

    // ---- phase 4: two groups of 4 channels ----
    #pragma unroll 1
    for (int g = 0; g < 2; g++) {
        // build W_eff^T [ch4][i*16 + o], o padded to 16 (pad = 0)
        for (int p = t; p < 4 * 960; p += NTHR) {
            int c4 = p / 960, q = p % 960;
            int i = q >> 4, o = q & 15;
            float v = 0.f;
            if (o < 15) {
                int idx = o * 60 + i;
                float m0 = __ldg(map_w + idx);
                float m1 = __ldg(map_w + 900 + idx);
                float m2 = __ldg(map_w + 1800 + idx);
                float m3 = __ldg(map_w + 2700 + idx);
                const float* gg = gts + (g * 4 + c4) * 4;
                v = gg[0] * m0 + gg[1] * m1 + gg[2] * m2 + gg[3] * m3;
            }
            wbuf[c4 * 960 + q] = v;
        }
        __syncthreads();

        // fold bias + mean-correction: bfin = b_eff*sd + mu*(1 - rowsum(W_eff))
        if (t < 60) {
            int c4 = t / 15, o = t % 15;
            int ch = g * 4 + c4;
            const float* gg = gts + ch * 4;
            float be = gg[0] * __ldg(map_b + o)      + gg[1] * __ldg(map_b + 15 + o)
                     + gg[2] * __ldg(map_b + 30 + o) + gg[3] * __ldg(map_b + 45 + o);
            float rw = 0.f;
            const float* Wc = wbuf + c4 * 960 + o;
            #pragma unroll
            for (int i = 0; i < NINV; i++) rw += Wc[i * 16];
            bfin[t] = be * stdv[ch] + meanv[ch] * (1.f - rw);
        }

        // register-tiled matmul on RAW x: tile = 4 outputs x 4 preds
        float4 A0, A1, A2, A3;
        int ch4 = 0, og = 0, sg = 0;
        const bool active = (t < 192);
        if (active) {
            ch4 = t / 48;
            int rem = t % 48;
            og = rem / 12;         // o0 = og*4 (og=3 covers o 12..14 + pad)
            sg = rem % 12;         // s0 = sg*4
            const float* row = xs + (g * 4 + ch4) * XROW + sg * 4;
            const float* Wp  = wbuf + ch4 * 960 + og * 4;
            A0 = make_float4(0.f, 0.f, 0.f, 0.f);
            A1 = A0; A2 = A0; A3 = A0;
            #pragma unroll 10
            for (int i = 0; i < NINV; i++) {
                float4 xv = *(const float4*)(row + i * SEGS);
                float4 wv = *(const float4*)(Wp + i * 16);
                A0.x = fmaf(wv.x, xv.x, A0.x);
                A0.y = fmaf(wv.x, xv.y, A0.y);
                A0.z = fmaf(wv.x, xv.z, A0.z);
                A0.w = fmaf(wv.x, xv.w, A0.w);
                A1.x = fmaf(wv.y, xv.x, A1.x);
                A1.y = fmaf(wv.y, xv.y, A1.y);
                A1.z = fmaf(wv.y, xv.z, A1.z);
                A1.w = fmaf(wv.y, xv.w, A1.w);
                A2.x = fmaf(wv.z, xv.x, A2.x);
                A2.y = fmaf(wv.z, xv.y, A2.y);
                A2.z = fmaf(wv.z, xv.z, A2.z);
                A2.w = fmaf(wv.z, xv.w, A2.w);
                A3.x = fmaf(wv.w, xv.x, A3.x);
                A3.y = fmaf(wv.w, xv.y, A3.y);
                A3.z = fmaf(wv.w, xv.z, A3.z);
                A3.w = fmaf(wv.w, xv.w, A3.w);
            }
        }
        __syncthreads();   // all x/W_eff reads done before staging overwrites xs
        if (active) {
            int ch = g * 4 + ch4;
            float* orow = xs + ch * XROW;
            int ob = ch4 * 15 + og * 4;
            float bb = bfin[ob];
            float4 r;
            r.x = A0.x + bb; r.y = A0.y + bb; r.z = A0.z + bb; r.w = A0.w + bb;
            *(float4*)(orow + (og * 4 + 0) * SEGS + sg * 4) = r;
            bb = bfin[ob + 1];
            r.x = A1.x + bb; r.y = A1.y + bb; r.z = A1.z + bb; r.w = A1.w + bb;
            *(float4*)(orow + (og * 4 + 1) * SEGS + sg * 4) = r;
            bb = bfin[ob + 2];
            r.x = A2.x + bb; r.y = A2.y + bb; r.z = A2.z + bb; r.w = A2.w + bb;
            *(float4*)(orow + (og * 4 + 2) * SEGS + sg * 4) = r;
            if (og < 3) {
                bb = bfin[ob + 3];
                r.x = A3.x + bb; r.y = A3.y + bb; r.z = A3.z + bb; r.w = A3.w + bb;
                *(float4*)(orow + (og * 4 + 3) * SEGS + sg * 4) = r;
            }
        }
        __syncthreads();   // group done; wbuf free for next group
    }

    // ---- phase 5: coalesced output write (float2, 2 channels) ----
    {
        const size_t obase = (size_t)b * PREDP * CC + c0;
        for (int idx = t; idx < 4 * PREDP; idx += NTHR) {
            int pr = idx & 3, p = idx >> 2;
            int c = c0 + pr * 2;
            float2 v;
            v.x = xs[(pr * 2) * XROW + p];
            v.y = xs[(pr * 2 + 1) * XROW + p];
            if (c + 1 < CC)
                *(float2*)(out + obase + (size_t)p * CC + pr * 2) = v;
            else if (c < CC)
                out[obase + (size_t)p * CC + pr * 2] = v.x;
        }
    }
}

extern "C" void kernel_launch(void* const* d_in, const int* in_sizes, int n_in,
                              void* d_out, int out_size)
{
    const float* x      = (const float*)d_in[0];
    const float* conv_w = (const float*)d_in[1];
    const float* conv_b = (const float*)d_in[2];
    const float* gate_w = (const float*)d_in[3];
    const float* gate_b = (const float*)d_in[4];
    const float* map_w  = (const float*)d_in[5];
    const float* map_b  = (const float*)d_in[6];
    float* out = (float*)d_out;

    const int smem_bytes = SMEM_FLOATS * (int)sizeof(float);   // 108,656 B
    cudaFuncSetAttribute(fused_model_kernel,
                         cudaFuncAttributeMaxDynamicSharedMemorySize, smem_bytes);

    dim3 grid(BB * CBLKS);   // 3456 blocks
    fused_model_kernel<<<grid, NTHR, smem_bytes>>>(x, conv_w, conv_b, gate_w,
                                                   gate_b, map_w, map_b, out);
}

// round 5
// speedup vs baseline: 1.6619x; 1.6619x over previous
#include <cuda_runtime.h>
#include <math.h>

// Problem constants
#define BB 32
#define LL 2880
#define CC 862
#define PREDP 720
#define SEGS 48
#define NMM 4
#define KK 16
#define NINV 60
#define NOUTV 15
#define CDIMV 359

#define CPB 8              // channels per block
#define XROW 2884          // padded smem row stride (floats), 2884 % 32 == 4
#define NTHR 256
#define CBLKS ((CC + CPB - 1) / CPB)   // 108

// smem layout (floats)
//  xs   : 8*2884 = 23072   raw x -> (reused) staged outputs
//  mw4  : 3600             map_w transposed [i][o*4+m], i-stride 60
//  gws  : 1436             gate_w staged
//  scr  : 256              shuffle-reduction scratch
//  cw 128, gts 32, meanv 8, stdv 8, istdv 8, cbs 8
#define SMEM_FLOATS (CPB*XROW + 3600 + 1436 + 256 + 128 + 32 + 8 + 8 + 8 + 8)

__global__ __launch_bounds__(NTHR, 2)
void fused_model_kernel(const float* __restrict__ x,
                        const float* __restrict__ conv_w,
                        const float* __restrict__ conv_b,
                        const float* __restrict__ gate_w,
                        const float* __restrict__ gate_b,
                        const float* __restrict__ map_w,
                        const float* __restrict__ map_b,
                        float* __restrict__ out)
{
    extern __shared__ float sm[];
    float* xs    = sm;                     // 23072
    float* smw   = xs + CPB * XROW;        // 3600
    float* gws   = smw + 3600;             // 1436
    float* scr   = gws + 1436;             // 256
    float* cw    = scr + 256;              // 128
    float* gts   = cw + 128;               // 32
    float* meanv = gts + 32;               // 8
    float* stdv  = meanv + 8;              // 8
    float* istdv = stdv + 8;               // 8
    float* cbs   = istdv + 8;              // 8

    const int t  = threadIdx.x;
    const int b  = blockIdx.x / CBLKS;
    const int c0 = (blockIdx.x % CBLKS) * CPB;

    // ---- phase 0: conv weights/bias ----
    if (t < CPB * KK) {
        int chh = t >> 4, k = t & 15;
        int c = c0 + chh;
        cw[t] = (c < CC) ? conv_w[c * KK + k] : 0.f;
    }
    if (t >= 128 && t < 128 + CPB) {
        int c = c0 + (t - 128);
        cbs[t - 128] = (c < CC) ? conv_b[c] : 0.f;
    }

    // ---- phase 1: load raw x (float2 channel-pairs) + stats partials,
    //      plus one-time smem staging of map_w (transposed) and gate_w ----
    {
        const int pr   = t & 3;            // channel pair 0..3
        const int lane = t >> 2;           // 0..63
        const int c    = c0 + pr * 2;
        const bool v0 = (c < CC), v1 = (c + 1 < CC);
        const float* xb = x + (size_t)b * LL * CC + c;
        float* r0 = xs + (pr * 2) * XROW;
        float* r1 = r0 + XROW;
        float s0 = 0.f, q0 = 0.f, s1 = 0.f, q1 = 0.f;
        if (v1) {
            #pragma unroll 5
            for (int l = lane; l < LL; l += 64) {
                float2 vv = *(const float2*)(xb + (size_t)l * CC);
                r0[l] = vv.x; r1[l] = vv.y;
                s0 += vv.x; q0 = fmaf(vv.x, vv.x, q0);
                s1 += vv.y; q1 = fmaf(vv.y, vv.y, q1);
            }
        } else {
            for (int l = lane; l < LL; l += 64) {
                float a = v0 ? __ldg(xb + (size_t)l * CC) : 0.f;
                r0[l] = a; r1[l] = 0.f;
                s0 += a; q0 = fmaf(a, a, q0);
            }
        }

        // build mw4[i*60 + o*4 + m] from map_w[m*900 + o*60 + i] (coalesced f4 LDG)
        for (int q = t; q < 900; q += NTHR) {
            int m = q / 225, r = q % 225;
            int o_ = r / 15, i4 = (r % 15) * 4;
            float4 v = *(const float4*)(map_w + m * 900 + o_ * 60 + i4);
            smw[(i4 + 0) * 60 + o_ * 4 + m] = v.x;
            smw[(i4 + 1) * 60 + o_ * 4 + m] = v.y;
            smw[(i4 + 2) * 60 + o_ * 4 + m] = v.z;
            smw[(i4 + 3) * 60 + o_ * 4 + m] = v.w;
        }
        // stage gate_w
        for (int i = t; i < NMM * CDIMV; i += NTHR)
            gws[i] = __ldg(gate_w + i);

        // warp-shuffle stats reduction over the 8 same-pair lanes
        #pragma unroll
        for (int off = 4; off <= 16; off <<= 1) {
            s0 += __shfl_xor_sync(0xffffffff, s0, off);
            s1 += __shfl_xor_sync(0xffffffff, s1, off);
            q0 += __shfl_xor_sync(0xffffffff, q0, off);
            q1 += __shfl_xor_sync(0xffffffff, q1, off);
        }
        if ((t & 31) < 4) {
            int w = t >> 5;
            float* p = scr + w * 16 + pr * 4;
            p[0] = s0; p[1] = s1; p[2] = q0; p[3] = q1;
        }
    }
    __syncthreads();

    if (t < 8) {
        int pr = t >> 1, e = t & 1;
        float s = 0.f, q = 0.f;
        #pragma unroll
        for (int w = 0; w < 8; w++) {
            s += scr[w * 16 + pr * 4 + e];
            q += scr[w * 16 + pr * 4 + 2 + e];
        }
        float mean = s * (1.f / LL);
        float var  = fmaxf(q * (1.f / LL) - mean * mean, 0.f);
        float sd   = sqrtf(var + 1e-10f);
        meanv[t] = mean;
        stdv[t]  = sd;
        istdv[t] = 1.f / sd;
    }
    __syncthreads();

    // ---- phase 3: depthwise conv on RAW x (normalize folded) + gate partials ----
    {
        const int ch = t & 7, dl = t >> 3;     // 32 d-lanes per channel
        const int d0 = dl * 12;
        const int dend = (d0 + 12 < CDIMV) ? d0 + 12 : CDIMV;
        float a0 = 0.f, a1 = 0.f, a2 = 0.f, a3 = 0.f;
        if (d0 < dend) {
            const float4* kwp = (const float4*)(cw + ch * 16);
            const float4 kA = kwp[0], kB = kwp[1], kC = kwp[2], kD = kwp[3];
            const float ksum = kA.x + kA.y + kA.z + kA.w + kB.x + kB.y + kB.z + kB.w
                             + kC.x + kC.y + kC.z + kC.w + kD.x + kD.y + kD.z + kD.w;
            const float scale  = istdv[ch];
            const float offset = cbs[ch] - meanv[ch] * ksum * scale;
            const float* row = xs + ch * XROW;
            const float4* base = (const float4*)(row + 8 * d0);
            float4 w0 = base[0], w1 = base[1], w2 = base[2], w3 = base[3];
            for (int d = d0; d < dend; d++) {
                float dot = 0.f;
                dot = fmaf(w0.x, kA.x, dot); dot = fmaf(w0.y, kA.y, dot);
                dot = fmaf(w0.z, kA.z, dot); dot = fmaf(w0.w, kA.w, dot);
                dot = fmaf(w1.x, kB.x, dot); dot = fmaf(w1.y, kB.y, dot);
                dot = fmaf(w1.z, kB.z, dot); dot = fmaf(w1.w, kB.w, dot);
                dot = fmaf(w2.x, kC.x, dot); dot = fmaf(w2.y, kC.y, dot);
                dot = fmaf(w2.z, kC.z, dot); dot = fmaf(w2.w, kC.w, dot);
                dot = fmaf(w3.x, kD.x, dot); dot = fmaf(w3.y, kD.y, dot);
                dot = fmaf(w3.z, kD.z, dot); dot = fmaf(w3.w, kD.w, dot);
                float cv = fmaf(dot, scale, offset);
                int j = d - d0;
                if (d + 1 < dend) {
                    w0 = w2; w1 = w3;
                    w2 = base[2 * j + 4];
                    w3 = base[2 * j + 5];
                }
                a0 = fmaf(cv, gws[d],             a0);
                a1 = fmaf(cv, gws[CDIMV + d],     a1);
                a2 = fmaf(cv, gws[2 * CDIMV + d], a2);
                a3 = fmaf(cv, gws[3 * CDIMV + d], a3);
            }
        }
        // reduce over the 4 same-channel lanes within the warp
        a0 += __shfl_xor_sync(0xffffffff, a0, 8);
        a0 += __shfl_xor_sync(0xffffffff, a0, 16);
        a1 += __shfl_xor_sync(0xffffffff, a1, 8);
        a1 += __shfl_xor_sync(0xffffffff, a1, 16);
        a2 += __shfl_xor_sync(0xffffffff, a2, 8);
        a2 += __shfl_xor_sync(0xffffffff, a2, 16);
        a3 += __shfl_xor_sync(0xffffffff, a3, 8);
        a3 += __shfl_xor_sync(0xffffffff, a3, 16);
        if ((t & 31) < 8) {
            int w = t >> 5;
            float* p = scr + w * 32 + ch * 4;
            p[0] = a0; p[1] = a1; p[2] = a2; p[3] = a3;
        }
    }
    __syncthreads();
    if (t < 32) {
        int ch = t >> 2, m = t & 3;
        float s = 0.f;
        #pragma unroll
        for (int w = 0; w < 8; w++) s += scr[w * 32 + ch * 4 + m];
        gts[ch * 4 + m] = s + __ldg(gate_b + m);
    }
    __syncwarp();
    if (t < CPB) {
        float g0 = gts[t * 4], g1 = gts[t * 4 + 1], g2 = gts[t * 4 + 2], g3 = gts[t * 4 + 3];
        float mx = fmaxf(fmaxf(g0, g1), fmaxf(g2, g3));
        g0 = expf(g0 - mx); g1 = expf(g1 - mx); g2 = expf(g2 - mx); g3 = expf(g3 - mx);
        float inv = 1.f / (g0 + g1 + g2 + g3);
        gts[t * 4]     = g0 * inv;
        gts[t * 4 + 1] = g1 * inv;
        gts[t * 4 + 2] = g2 * inv;
        gts[t * 4 + 3] = g3 * inv;
    }
    __syncthreads();

    // ---- phase 4: map matmul, thread = (ch, o), 12 float4 accumulators (f32x2 FMA) ----
    unsigned long long acc[24];
    float bfin = 0.f;
    int ch = 0, o = 0;
    bool act = false;
    if (t < 128) {
        ch = t >> 4;
        o  = t & 15;
        act = (o < NOUTV);
        const int oo = act ? o : 14;          // clamp inactive lanes to a safe address
        const float4 gv = *(const float4*)(gts + ch * 4);
        const float g0 = gv.x, g1 = gv.y, g2 = gv.z, g3 = gv.w;
        const float* row = xs + ch * XROW;
        unsigned int rowa = (unsigned int)__cvta_generic_to_shared(row);
        const float* mwp = smw + oo * 4;
        #pragma unroll
        for (int s = 0; s < 24; s++) acc[s] = 0ULL;
        float rw = 0.f;
        #pragma unroll 4
        for (int i = 0; i < NINV; i++) {
            float4 mw = *(const float4*)(mwp + i * 60);
            float w = g0 * mw.x;
            w = fmaf(g1, mw.y, w);
            w = fmaf(g2, mw.z, w);
            w = fmaf(g3, mw.w, w);
            rw += w;
            unsigned long long w2;
            asm("mov.b64 %0, {%1, %1};" : "=l"(w2) : "f"(w));
            unsigned int xa = rowa + (unsigned int)(i * SEGS * 4);
            #pragma unroll
            for (int s = 0; s < 12; s++) {
                unsigned long long x0, x1;
                asm("ld.shared.v2.u64 {%0, %1}, [%2];"
                    : "=l"(x0), "=l"(x1) : "r"(xa + s * 16));
                asm("fma.rn.f32x2 %0, %1, %2, %0;" : "+l"(acc[2 * s])     : "l"(w2), "l"(x0));
                asm("fma.rn.f32x2 %0, %1, %2, %0;" : "+l"(acc[2 * s + 1]) : "l"(w2), "l"(x1));
            }
        }
        if (act) {
            float be = g0 * __ldg(map_b + o)          + g1 * __ldg(map_b + NOUTV + o)
                     + g2 * __ldg(map_b + 2 * NOUTV + o) + g3 * __ldg(map_b + 3 * NOUTV + o);
            bfin = be * stdv[ch] + meanv[ch] * (1.f - rw);
        }
    }
    __syncthreads();   // all x reads complete before staging overwrites xs
    if (t < 128 && act) {
        float* orow = xs + ch * XROW;
        #pragma unroll
        for (int s = 0; s < 12; s++) {
            float l0, h0, l1, h1;
            asm("mov.b64 {%0, %1}, %2;" : "=f"(l0), "=f"(h0) : "l"(acc[2 * s]));
            asm("mov.b64 {%0, %1}, %2;" : "=f"(l1), "=f"(h1) : "l"(acc[2 * s + 1]));
            float4 r = make_float4(l0 + bfin, h0 + bfin, l1 + bfin, h1 + bfin);
            *(float4*)(orow + o * SEGS + s * 4) = r;
        }
    }
    __syncthreads();

    // ---- phase 5: coalesced output write (float2 over channel pairs) ----
    {
        const size_t obase = (size_t)b * PREDP * CC + c0;
        for (int idx = t; idx < 4 * PREDP; idx += NTHR) {
            int pr = idx & 3, p = idx >> 2;
            int c = c0 + pr * 2;
            float2 v;
            v.x = xs[(pr * 2) * XROW + p];
            v.y = xs[(pr * 2 + 1) * XROW + p];
            if (c + 1 < CC)
                *(float2*)(out + obase + (size_t)p * CC + pr * 2) = v;
            else if (c < CC)
                out[obase + (size_t)p * CC + pr * 2] = v.x;
        }
    }
}

extern "C" void kernel_launch(void* const* d_in, const int* in_sizes, int n_in,
                              void* d_out, int out_size)
{
    const float* x      = (const float*)d_in[0];
    const float* conv_w = (const float*)d_in[1];
    const float* conv_b = (const float*)d_in[2];
    const float* gate_w = (const float*)d_in[3];
    const float* gate_b = (const float*)d_in[4];
    const float* map_w  = (const float*)d_in[5];
    const float* map_b  = (const float*)d_in[6];
    float* out = (float*)d_out;

    const int smem_bytes = SMEM_FLOATS * (int)sizeof(float);   // 114,224 B
    cudaFuncSetAttribute(fused_model_kernel,
                         cudaFuncAttributeMaxDynamicSharedMemorySize, smem_bytes);

    dim3 grid(BB * CBLKS);   // 3456 blocks
    fused_model_kernel<<<grid, NTHR, smem_bytes>>>(x, conv_w, conv_b, gate_w,
                                                   gate_b, map_w, map_b, out);
}